// round 4
// baseline (speedup 1.0000x reference)
#include <cuda_runtime.h>

#define BB 16
#define SS 2048
#define KK 16
#define LL 64
#define II 256
#define NS (BB*SS)        // 32768
#define CH 64
#define NC (SS/CH)        // 32 chunks per batch
#define TOTCH (BB*NC)     // 512 chunks total

#define SPB 16            // samples per emissions block
#define TPB 256

#define FULL 0xffffffffu

// Scratch (device globals; no allocation allowed)
__device__ float g_E[NS*KK];           // exp(clamp(em - rowmax, -80))
__device__ float g_emp[NS*KK];         // em - rowmax
__device__ float g_rowmax[NS];
__device__ float g_invvar[KK*LL];
__device__ float g_lvsum[KK];
__device__ float g_ws2[KK];
__device__ float g_A[KK*KK];           // row-softmaxed transition matrix
__device__ float g_Rn[TOTCH][KK*KK];   // per-chunk matrix, rows normalized
__device__ float g_rowlog[TOTCH][KK];  // per-row log scale
__device__ float g_rmsum[TOTCH];       // sum of rowmax over chunk steps
__device__ float g_qb[TOTCH][KK];      // boundary q at chunk start (chunks >= 1)
__device__ float g_Cb[TOTCH];

// ---------------------------------------------------------------------------
// Setup: one warp-block per state k.
// ---------------------------------------------------------------------------
__global__ void __launch_bounds__(32) setup_kernel(
    const float* __restrict__ prior_logvar,
    const float* __restrict__ Ws,
    const float* __restrict__ trans)
{
    int w = blockIdx.x;
    int lane = threadIdx.x;

    // invvar + lvsum (row w, 64 elems, 2 per lane)
    float s = 0.f;
    #pragma unroll
    for (int e = 0; e < 2; e++) {
        int idx = w*LL + lane + 32*e;
        float lv = __ldg(prior_logvar + idx);
        g_invvar[idx] = 1.0f / (expf(lv) + 1e-8f);
        s += lv;
    }
    #pragma unroll
    for (int off = 16; off; off >>= 1) s += __shfl_xor_sync(FULL, s, off);
    if (lane == 0) g_lvsum[w] = s;

    // ||Ws_w||^2
    float s2 = 0.f;
    #pragma unroll
    for (int e = 0; e < 8; e++) {
        float v = __ldg(Ws + w*II + lane + 32*e);
        s2 = fmaf(v, v, s2);
    }
    #pragma unroll
    for (int off = 16; off; off >>= 1) s2 += __shfl_xor_sync(FULL, s2, off);
    if (lane == 0) g_ws2[w] = s2;

    // row-softmax of trans (lanes 0..15 active)
    float v = (lane < 16) ? __ldg(trans + w*KK + (lane & 15)) : -1e30f;
    float mx = v;
    #pragma unroll
    for (int off = 8; off; off >>= 1) mx = fmaxf(mx, __shfl_xor_sync(FULL, mx, off));
    float ex = (lane < 16) ? expf(v - mx) : 0.f;
    float se = ex;
    #pragma unroll
    for (int off = 8; off; off >>= 1) se += __shfl_xor_sync(FULL, se, off);
    if (lane < 16) g_A[w*KK + lane] = expf(v - mx - logf(se));
}

// ---------------------------------------------------------------------------
// Emissions
// ---------------------------------------------------------------------------
__global__ void __launch_bounds__(TPB) emissions_kernel(
    const float* __restrict__ Y, const float* __restrict__ Z,
    const float* __restrict__ Wz, const float* __restrict__ Ws,
    const float* __restrict__ bdec, const float* __restrict__ mu)
{
    __shared__ __align__(16) float z_a[LL][SPB];      // [l][s]
    __shared__ __align__(16) float z_b[SPB][LL+4];    // [s][l] padded
    __shared__ __align__(16) float d_sh[SPB][II];
    __shared__ __align__(16) float ws_sh[KK][II+4];

    int tid = threadIdx.x;
    int s0 = blockIdx.x * SPB;

    #pragma unroll
    for (int e = 0; e < (SPB*LL)/TPB; e++) {
        int idx = tid + TPB*e;
        int s = idx >> 6, l = idx & 63;
        float v = Z[(s0 + s)*LL + l];
        z_a[l][s] = v;
        z_b[s][l] = v;
    }
    #pragma unroll
    for (int e = 0; e < (KK*II)/TPB; e++) {
        int idx = tid + TPB*e;
        ws_sh[idx >> 8][idx & 255] = Ws[idx];
    }
    __syncthreads();

    // ---- Phase A: base = b_dec + z @ Wz; d = y - base ----
    {
        float base[SPB];
        float bd = __ldg(bdec + tid);
        #pragma unroll
        for (int s = 0; s < SPB; s++) base[s] = bd;

        #pragma unroll 4
        for (int l = 0; l < LL; l++) {
            float wz = __ldg(Wz + l*II + tid);
            const float4* zr = (const float4*)&z_a[l][0];
            float4 za = zr[0], zb = zr[1], zc = zr[2], zd = zr[3];
            base[0]  = fmaf(za.x, wz, base[0]);
            base[1]  = fmaf(za.y, wz, base[1]);
            base[2]  = fmaf(za.z, wz, base[2]);
            base[3]  = fmaf(za.w, wz, base[3]);
            base[4]  = fmaf(zb.x, wz, base[4]);
            base[5]  = fmaf(zb.y, wz, base[5]);
            base[6]  = fmaf(zb.z, wz, base[6]);
            base[7]  = fmaf(zb.w, wz, base[7]);
            base[8]  = fmaf(zc.x, wz, base[8]);
            base[9]  = fmaf(zc.y, wz, base[9]);
            base[10] = fmaf(zc.z, wz, base[10]);
            base[11] = fmaf(zc.w, wz, base[11]);
            base[12] = fmaf(zd.x, wz, base[12]);
            base[13] = fmaf(zd.y, wz, base[13]);
            base[14] = fmaf(zd.z, wz, base[14]);
            base[15] = fmaf(zd.w, wz, base[15]);
        }
        #pragma unroll
        for (int s = 0; s < SPB; s++) {
            float y = __ldg(Y + (s0 + s)*II + tid);
            d_sh[s][tid] = y - base[s];
        }
    }
    __syncthreads();

    // ---- Phase B: thread (sample, state) ----
    int si = tid >> 4;
    int k  = tid & 15;

    float sd = 0.f;
    #pragma unroll
    for (int t = 0; t < 16; t++) {
        float dv = d_sh[si][t*16 + k];
        sd = fmaf(dv, dv, sd);
    }
    #pragma unroll
    for (int off = 8; off; off >>= 1) sd += __shfl_xor_sync(FULL, sd, off);

    float a0 = 0.f, a1 = 0.f, a2 = 0.f, a3 = 0.f;
    const float4* dr = (const float4*)&d_sh[si][0];
    const float4* wr = (const float4*)&ws_sh[k][0];
    #pragma unroll 8
    for (int i4 = 0; i4 < II/4; i4++) {
        float4 dv = dr[i4], wv = wr[i4];
        a0 = fmaf(dv.x, wv.x, a0);
        a1 = fmaf(dv.y, wv.y, a1);
        a2 = fmaf(dv.z, wv.z, a2);
        a3 = fmaf(dv.w, wv.w, a3);
    }
    float dot = (a0 + a1) + (a2 + a3);
    float accy = sd - 2.f*dot + __ldg(&g_ws2[k]);

    float b0 = 0.f, b1 = 0.f, b2 = 0.f, b3 = 0.f;
    const float4* zr = (const float4*)&z_b[si][0];
    const float4* mr = (const float4*)(mu + k*LL);
    const float4* ir = (const float4*)(g_invvar + k*LL);
    #pragma unroll
    for (int l4 = 0; l4 < LL/4; l4++) {
        float4 zv = zr[l4];
        float4 mv = __ldg(mr + l4);
        float4 iv = __ldg(ir + l4);
        float t0 = zv.x - mv.x; b0 = fmaf(t0*t0, iv.x, b0);
        float t1 = zv.y - mv.y; b1 = fmaf(t1*t1, iv.y, b1);
        float t2 = zv.z - mv.z; b2 = fmaf(t2*t2, iv.z, b2);
        float t3 = zv.w - mv.w; b3 = fmaf(t3*t3, iv.w, b3);
    }
    float accz = (b0 + b1) + (b2 + b3);

    const float LLOG2PI = 117.62413f;  // 64 * log(2*pi)
    float em = -0.5f*accy - 0.5f*(__ldg(&g_lvsum[k]) + accz + LLOG2PI);

    float m = em;
    #pragma unroll
    for (int off = 8; off; off >>= 1)
        m = fmaxf(m, __shfl_xor_sync(FULL, m, off));

    float emp = em - m;
    float E = __expf(fmaxf(emp, -80.f));

    int sample = s0 + si;
    g_E[sample*KK + k]   = E;
    g_emp[sample*KK + k] = emp;
    if (k == 0) g_rowmax[sample] = m;
}

// ---------------------------------------------------------------------------
// Phase 1: per-chunk matrix product R_c = prod M_t, M_t = A diag(E_t).
// One warp per chunk. Lane (i = lane>>1, half h = lane&1) owns R[i][h*8+kk].
// ---------------------------------------------------------------------------
__global__ void __launch_bounds__(32) phase1_kernel() {
    int c = blockIdx.x;
    int lane = threadIdx.x;
    int b = c / NC, cl = c % NC;
    int i = lane >> 1, h = lane & 1;

    float a[KK][8];
    #pragma unroll
    for (int j = 0; j < KK; j++)
        #pragma unroll
        for (int kk = 0; kk < 8; kk++)
            a[j][kk] = g_A[j*KK + h*8 + kk];

    float R[8];
    #pragma unroll
    for (int kk = 0; kk < 8; kk++)
        R[kk] = (i == h*8 + kk) ? 1.f : 0.f;

    float rowlog = 0.f, rmsum = 0.f;

    int t0 = b*SS + cl*CH;
    int us = (cl == 0) ? 1 : 0;
    const float* prm = g_rowmax + t0;

    // prefetch E for first step (SoA: 2 contiguous float4)
    float E[8], En[8];
    {
        const float4* p4 = (const float4*)(g_E + (size_t)(t0 + us)*KK + h*8);
        float4 q0 = __ldg(p4+0), q1 = __ldg(p4+1);
        E[0]=q0.x; E[1]=q0.y; E[2]=q0.z; E[3]=q0.w;
        E[4]=q1.x; E[5]=q1.y; E[6]=q1.z; E[7]=q1.w;
    }
    float rmc = __ldg(prm + us), rmn = 0.f;

    for (int u = us; u < CH; u++) {
        if (u + 1 < CH) {
            const float4* p4 = (const float4*)(g_E + (size_t)(t0 + u + 1)*KK + h*8);
            float4 q0 = __ldg(p4+0), q1 = __ldg(p4+1);
            En[0]=q0.x; En[1]=q0.y; En[2]=q0.z; En[3]=q0.w;
            En[4]=q1.x; En[5]=q1.y; En[6]=q1.z; En[7]=q1.w;
            rmn = __ldg(prm + u + 1);
        }
        rmsum += rmc;

        float rp[8];
        #pragma unroll
        for (int j = 0; j < 8; j++) rp[j] = __shfl_xor_sync(FULL, R[j], 1);
        float rlo[8], rhi[8];
        #pragma unroll
        for (int j = 0; j < 8; j++) {
            rlo[j] = h ? rp[j] : R[j];
            rhi[j] = h ? R[j] : rp[j];
        }
        float nw[8];
        #pragma unroll
        for (int kk = 0; kk < 8; kk++) {
            float s0 = 0.f, s1 = 0.f;
            #pragma unroll
            for (int j = 0; j < 8; j++) {
                s0 = fmaf(rlo[j], a[j][kk],   s0);
                s1 = fmaf(rhi[j], a[j+8][kk], s1);
            }
            nw[kk] = (s0 + s1) * E[kk];
        }
        #pragma unroll
        for (int kk = 0; kk < 8; kk++) R[kk] = nw[kk];

        if (((u + 1) & 15) == 0) {
            float mx = R[0];
            #pragma unroll
            for (int kk = 1; kk < 8; kk++) mx = fmaxf(mx, R[kk]);
            mx = fmaxf(mx, __shfl_xor_sync(FULL, mx, 1));
            mx = fmaxf(mx, 1e-37f);
            float inv = __fdividef(1.f, mx);
            #pragma unroll
            for (int kk = 0; kk < 8; kk++) R[kk] *= inv;
            rowlog += __logf(mx);
        }

        #pragma unroll
        for (int kk = 0; kk < 8; kk++) E[kk] = En[kk];
        rmc = rmn;
    }

    #pragma unroll
    for (int kk = 0; kk < 8; kk++)
        g_Rn[c][i*KK + h*8 + kk] = R[kk];
    if (h == 0) g_rowlog[c][i] = rowlog;
    if (lane == 0) g_rmsum[c] = rmsum;
}

// ---------------------------------------------------------------------------
// Phase 2: sequential combine over chunks (one warp per batch).
// All exp/log work is done off the dependent chain; per-chunk chain is
// mult + 16-shfl-dot + 4-shfl max + rcp.
// ---------------------------------------------------------------------------
__global__ void __launch_bounds__(32) phase2_kernel(const float* __restrict__ start_logits) {
    int b = blockIdx.x;
    int lane = threadIdx.x;
    int kk = lane & 15;

    // log_softmax(start)
    float sv = __ldg(start_logits + kk);
    float sm = sv;
    #pragma unroll
    for (int off = 8; off; off >>= 1) sm = fmaxf(sm, __shfl_xor_sync(FULL, sm, off));
    float se = __expf(sv - sm);
    #pragma unroll
    for (int off = 8; off; off >>= 1) se += __shfl_xor_sync(FULL, se, off);
    float lstart = sv - sm - __logf(se);

    // init: state after step 0
    float e0 = g_emp[(size_t)(b*SS)*KK + kk];
    float t = lstart + e0;
    float m0 = t;
    #pragma unroll
    for (int off = 8; off; off >>= 1) m0 = fmaxf(m0, __shfl_xor_sync(FULL, m0, off));
    float q = __expf(t - m0);
    float C = __ldg(&g_rowmax[b*SS]) + m0;

    // Prepare chunk 0: Bcol[i] = exp(rowlog[i]-rlmax) * Rn[i][kk]
    float Bcol[16], rlmax, rs;
    {
        int gc = b*NC;
        float rl = __ldg(&g_rowlog[gc][kk]);
        rlmax = rl;
        #pragma unroll
        for (int off = 8; off; off >>= 1) rlmax = fmaxf(rlmax, __shfl_xor_sync(FULL, rlmax, off));
        float smy = __expf(rl - rlmax);
        #pragma unroll
        for (int i = 0; i < 16; i++) {
            float si_ = __shfl_sync(FULL, smy, i);
            Bcol[i] = si_ * __ldg(&g_Rn[gc][i*KK + kk]);
        }
        rs = __ldg(&g_rmsum[gc]);
    }

    for (int c = 0; c < NC; c++) {
        int gc = b*NC + c;
        if (c > 0) {
            if (lane < 16) g_qb[gc][kk] = q;
            if (lane == 0) g_Cb[gc] = C;
        }
        // prefetch + prep next chunk (off critical chain)
        float Bn[16], rlmaxn = 0.f, rsn = 0.f;
        if (c + 1 < NC) {
            float rl = __ldg(&g_rowlog[gc+1][kk]);
            rlmaxn = rl;
            #pragma unroll
            for (int off = 8; off; off >>= 1) rlmaxn = fmaxf(rlmaxn, __shfl_xor_sync(FULL, rlmaxn, off));
            float smy = __expf(rl - rlmaxn);
            #pragma unroll
            for (int i = 0; i < 16; i++) {
                float si_ = __shfl_sync(FULL, smy, i);
                Bn[i] = si_ * __ldg(&g_Rn[gc+1][i*KK + kk]);
            }
            rsn = __ldg(&g_rmsum[gc+1]);
        }

        // combine (linear space): v[kk] = sum_i q[i] * Bcol[i]
        float s0 = 0.f, s1 = 0.f, s2 = 0.f, s3 = 0.f;
        #pragma unroll
        for (int j = 0; j < 16; j += 4) {
            s0 = fmaf(__shfl_sync(FULL, q, j + 0), Bcol[j + 0], s0);
            s1 = fmaf(__shfl_sync(FULL, q, j + 1), Bcol[j + 1], s1);
            s2 = fmaf(__shfl_sync(FULL, q, j + 2), Bcol[j + 2], s2);
            s3 = fmaf(__shfl_sync(FULL, q, j + 3), Bcol[j + 3], s3);
        }
        float v = (s0 + s1) + (s2 + s3);
        float mv = v;
        #pragma unroll
        for (int off = 8; off; off >>= 1) mv = fmaxf(mv, __shfl_xor_sync(FULL, mv, off));
        mv = fmaxf(mv, 1e-37f);
        q = __fdividef(v, mv);
        C += rs + rlmax + __logf(mv);

        #pragma unroll
        for (int i = 0; i < 16; i++) Bcol[i] = Bn[i];
        rlmax = rlmaxn; rs = rsn;
    }
}

// ---------------------------------------------------------------------------
// Phase 3: per-chunk vector recursion from stored boundary, writes outputs.
// ---------------------------------------------------------------------------
__global__ void __launch_bounds__(32) phase3_kernel(
    const float* __restrict__ start_logits, float* __restrict__ out)
{
    int c = blockIdx.x;
    int lane = threadIdx.x;
    int b = c / NC, cl = c % NC;
    int kk = lane & 15;

    float acol[KK];
    #pragma unroll
    for (int j = 0; j < KK; j++) acol[j] = __ldg(&g_A[j*KK + kk]);

    const float* pE = g_E   + (size_t)(b*SS + cl*CH)*KK;
    const float* pP = g_emp + (size_t)(b*SS + cl*CH)*KK;
    const float* prm = g_rowmax + b*SS + cl*CH;
    float* ob = out + (size_t)(b*SS + cl*CH)*KK;

    float bufEA[16], bufPA[16], bufEB[16], bufPB[16];
    float rmA[16], rmB[16];
    #pragma unroll
    for (int u = 0; u < 16; u++) {
        bufEA[u] = __ldg(pE + u*KK + kk);
        bufPA[u] = __ldg(pP + u*KK + kk);
        rmA[u]   = __ldg(prm + u);
    }

    float q, C;
    if (cl == 0) {
        float sv = __ldg(start_logits + kk);
        float sm = sv;
        #pragma unroll
        for (int off = 8; off; off >>= 1) sm = fmaxf(sm, __shfl_xor_sync(FULL, sm, off));
        float se = __expf(sv - sm);
        #pragma unroll
        for (int off = 8; off; off >>= 1) se += __shfl_xor_sync(FULL, se, off);
        float lstart = sv - sm - __logf(se);

        float a0 = lstart + bufPA[0] + rmA[0];
        if (lane < 16) ob[kk] = a0;
        q = __expf(fmaxf(lstart + bufPA[0], -80.f));
        C = rmA[0];
    } else {
        q = __ldg(&g_qb[c][kk]);
        C = __ldg(&g_Cb[c]);
    }

    const int NSB = CH / 16;  // 4
    for (int sb = 0; sb < NSB; sb++) {
        if (sb + 1 < NSB) {
            #pragma unroll
            for (int u = 0; u < 16; u++) {
                bufEB[u] = __ldg(pE + ((sb+1)*16 + u)*KK + kk);
                bufPB[u] = __ldg(pP + ((sb+1)*16 + u)*KK + kk);
                rmB[u]   = __ldg(prm + (sb+1)*16 + u);
            }
        }
        #pragma unroll
        for (int u = 0; u < 16; u++) {
            if (sb == 0 && u == 0 && cl == 0) continue;
            float s0 = 0.f, s1 = 0.f, s2 = 0.f, s3 = 0.f;
            #pragma unroll
            for (int j = 0; j < KK; j += 4) {
                s0 = fmaf(__shfl_sync(FULL, q, j + 0), acol[j + 0], s0);
                s1 = fmaf(__shfl_sync(FULL, q, j + 1), acol[j + 1], s1);
                s2 = fmaf(__shfl_sync(FULL, q, j + 2), acol[j + 2], s2);
                s3 = fmaf(__shfl_sync(FULL, q, j + 3), acol[j + 3], s3);
            }
            float ssum = (s0 + s1) + (s2 + s3);
            float ov = C + rmA[u] + bufPA[u] + __logf(ssum);
            if (lane < 16) ob[(sb*16 + u)*KK + kk] = ov;
            q = ssum * bufEA[u];
            C += rmA[u];
        }
        float mq = q;
        #pragma unroll
        for (int off = 16; off; off >>= 1)
            mq = fmaxf(mq, __shfl_xor_sync(FULL, mq, off));
        q = __fdividef(q, mq);
        C += __logf(mq);

        if (sb + 1 < NSB) {
            #pragma unroll
            for (int u = 0; u < 16; u++) {
                bufEA[u] = bufEB[u]; bufPA[u] = bufPB[u]; rmA[u] = rmB[u];
            }
        }
    }
}

// ---------------------------------------------------------------------------
extern "C" void kernel_launch(void* const* d_in, const int* in_sizes, int n_in,
                              void* d_out, int out_size) {
    const float* y   = (const float*)d_in[0];
    const float* z   = (const float*)d_in[1];
    const float* st  = (const float*)d_in[2];
    const float* tr  = (const float*)d_in[3];
    const float* mu  = (const float*)d_in[4];
    const float* lv  = (const float*)d_in[5];
    const float* wz  = (const float*)d_in[6];
    const float* ws  = (const float*)d_in[7];
    const float* bd  = (const float*)d_in[8];
    float* out = (float*)d_out;

    setup_kernel<<<KK, 32>>>(lv, ws, tr);
    emissions_kernel<<<NS/SPB, TPB>>>(y, z, wz, ws, bd, mu);
    phase1_kernel<<<TOTCH, 32>>>();
    phase2_kernel<<<BB, 32>>>(st);
    phase3_kernel<<<TOTCH, 32>>>(st, out);
}

// round 5
// speedup vs baseline: 1.0635x; 1.0635x over previous
#include <cuda_runtime.h>

#define BB 16
#define SS 2048
#define KK 16
#define LL 64
#define II 256
#define NS (BB*SS)        // 32768
#define CH 64
#define NC (SS/CH)        // 32 chunks per batch
#define TOTCH (BB*NC)     // 512 chunks total

#define SPB 16            // samples per emissions block
#define TPB 256

#define FULL 0xffffffffu

// Scratch (device globals; no allocation allowed)
__device__ float g_E[NS*KK];           // exp(clamp(em - rowmax, -80))
__device__ float g_emp[NS*KK];         // em - rowmax
__device__ float g_rowmax[NS];
__device__ float g_invvar[KK*LL];
__device__ float g_lvsum[KK];
__device__ float g_ws2[KK];
__device__ float g_A[KK*KK];           // row-softmaxed transition matrix
__device__ float g_Rn[TOTCH][KK*KK];   // per-chunk matrix, rows normalized
__device__ float g_rowlog[TOTCH][KK];  // per-row log scale
__device__ float g_rmsum[TOTCH];       // sum of rowmax over chunk steps
__device__ float g_qb[TOTCH][KK];      // boundary q at chunk start (chunks >= 1)
__device__ float g_Cb[TOTCH];

// ---------------------------------------------------------------------------
// Setup: one warp-block per state k.
// ---------------------------------------------------------------------------
__global__ void __launch_bounds__(32) setup_kernel(
    const float* __restrict__ prior_logvar,
    const float* __restrict__ Ws,
    const float* __restrict__ trans)
{
    int w = blockIdx.x;
    int lane = threadIdx.x;

    float s = 0.f;
    #pragma unroll
    for (int e = 0; e < 2; e++) {
        int idx = w*LL + lane + 32*e;
        float lv = __ldg(prior_logvar + idx);
        g_invvar[idx] = 1.0f / (expf(lv) + 1e-8f);
        s += lv;
    }
    #pragma unroll
    for (int off = 16; off; off >>= 1) s += __shfl_xor_sync(FULL, s, off);
    if (lane == 0) g_lvsum[w] = s;

    float s2 = 0.f;
    #pragma unroll
    for (int e = 0; e < 8; e++) {
        float v = __ldg(Ws + w*II + lane + 32*e);
        s2 = fmaf(v, v, s2);
    }
    #pragma unroll
    for (int off = 16; off; off >>= 1) s2 += __shfl_xor_sync(FULL, s2, off);
    if (lane == 0) g_ws2[w] = s2;

    float v = (lane < 16) ? __ldg(trans + w*KK + (lane & 15)) : -1e30f;
    float mx = v;
    #pragma unroll
    for (int off = 8; off; off >>= 1) mx = fmaxf(mx, __shfl_xor_sync(FULL, mx, off));
    float ex = (lane < 16) ? expf(v - mx) : 0.f;
    float se = ex;
    #pragma unroll
    for (int off = 8; off; off >>= 1) se += __shfl_xor_sync(FULL, se, off);
    if (lane < 16) g_A[w*KK + lane] = expf(v - mx - logf(se));
}

// ---------------------------------------------------------------------------
// Emissions
// ---------------------------------------------------------------------------
__global__ void __launch_bounds__(TPB) emissions_kernel(
    const float* __restrict__ Y, const float* __restrict__ Z,
    const float* __restrict__ Wz, const float* __restrict__ Ws,
    const float* __restrict__ bdec, const float* __restrict__ mu)
{
    __shared__ __align__(16) float z_a[LL][SPB];      // [l][s]
    __shared__ __align__(16) float z_b[SPB][LL+4];    // [s][l] padded
    __shared__ __align__(16) float d_sh[SPB][II];
    __shared__ __align__(16) float ws_sh[KK][II+4];

    int tid = threadIdx.x;
    int s0 = blockIdx.x * SPB;

    #pragma unroll
    for (int e = 0; e < (SPB*LL)/TPB; e++) {
        int idx = tid + TPB*e;
        int s = idx >> 6, l = idx & 63;
        float v = Z[(s0 + s)*LL + l];
        z_a[l][s] = v;
        z_b[s][l] = v;
    }
    #pragma unroll
    for (int e = 0; e < (KK*II)/TPB; e++) {
        int idx = tid + TPB*e;
        ws_sh[idx >> 8][idx & 255] = Ws[idx];
    }
    __syncthreads();

    // ---- Phase A: base = b_dec + z @ Wz; d = y - base ----
    {
        float base[SPB];
        float bd = __ldg(bdec + tid);
        #pragma unroll
        for (int s = 0; s < SPB; s++) base[s] = bd;

        #pragma unroll 4
        for (int l = 0; l < LL; l++) {
            float wz = __ldg(Wz + l*II + tid);
            const float4* zr = (const float4*)&z_a[l][0];
            float4 za = zr[0], zb = zr[1], zc = zr[2], zd = zr[3];
            base[0]  = fmaf(za.x, wz, base[0]);
            base[1]  = fmaf(za.y, wz, base[1]);
            base[2]  = fmaf(za.z, wz, base[2]);
            base[3]  = fmaf(za.w, wz, base[3]);
            base[4]  = fmaf(zb.x, wz, base[4]);
            base[5]  = fmaf(zb.y, wz, base[5]);
            base[6]  = fmaf(zb.z, wz, base[6]);
            base[7]  = fmaf(zb.w, wz, base[7]);
            base[8]  = fmaf(zc.x, wz, base[8]);
            base[9]  = fmaf(zc.y, wz, base[9]);
            base[10] = fmaf(zc.z, wz, base[10]);
            base[11] = fmaf(zc.w, wz, base[11]);
            base[12] = fmaf(zd.x, wz, base[12]);
            base[13] = fmaf(zd.y, wz, base[13]);
            base[14] = fmaf(zd.z, wz, base[14]);
            base[15] = fmaf(zd.w, wz, base[15]);
        }
        #pragma unroll
        for (int s = 0; s < SPB; s++) {
            float y = __ldg(Y + (s0 + s)*II + tid);
            d_sh[s][tid] = y - base[s];
        }
    }
    __syncthreads();

    // ---- Phase B: thread (sample, state) ----
    int si = tid >> 4;
    int k  = tid & 15;

    float sd = 0.f;
    #pragma unroll
    for (int t = 0; t < 16; t++) {
        float dv = d_sh[si][t*16 + k];
        sd = fmaf(dv, dv, sd);
    }
    #pragma unroll
    for (int off = 8; off; off >>= 1) sd += __shfl_xor_sync(FULL, sd, off);

    float a0 = 0.f, a1 = 0.f, a2 = 0.f, a3 = 0.f;
    const float4* dr = (const float4*)&d_sh[si][0];
    const float4* wr = (const float4*)&ws_sh[k][0];
    #pragma unroll 8
    for (int i4 = 0; i4 < II/4; i4++) {
        float4 dv = dr[i4], wv = wr[i4];
        a0 = fmaf(dv.x, wv.x, a0);
        a1 = fmaf(dv.y, wv.y, a1);
        a2 = fmaf(dv.z, wv.z, a2);
        a3 = fmaf(dv.w, wv.w, a3);
    }
    float dot = (a0 + a1) + (a2 + a3);
    float accy = sd - 2.f*dot + __ldg(&g_ws2[k]);

    float b0 = 0.f, b1 = 0.f, b2 = 0.f, b3 = 0.f;
    const float4* zr = (const float4*)&z_b[si][0];
    const float4* mr = (const float4*)(mu + k*LL);
    const float4* ir = (const float4*)(g_invvar + k*LL);
    #pragma unroll
    for (int l4 = 0; l4 < LL/4; l4++) {
        float4 zv = zr[l4];
        float4 mv = __ldg(mr + l4);
        float4 iv = __ldg(ir + l4);
        float t0 = zv.x - mv.x; b0 = fmaf(t0*t0, iv.x, b0);
        float t1 = zv.y - mv.y; b1 = fmaf(t1*t1, iv.y, b1);
        float t2 = zv.z - mv.z; b2 = fmaf(t2*t2, iv.z, b2);
        float t3 = zv.w - mv.w; b3 = fmaf(t3*t3, iv.w, b3);
    }
    float accz = (b0 + b1) + (b2 + b3);

    const float LLOG2PI = 117.62413f;  // 64 * log(2*pi)
    float em = -0.5f*accy - 0.5f*(__ldg(&g_lvsum[k]) + accz + LLOG2PI);

    float m = em;
    #pragma unroll
    for (int off = 8; off; off >>= 1)
        m = fmaxf(m, __shfl_xor_sync(FULL, m, off));

    float emp = em - m;
    float E = __expf(fmaxf(emp, -80.f));

    int sample = s0 + si;
    g_E[sample*KK + k]   = E;
    g_emp[sample*KK + k] = emp;
    if (k == 0) g_rowmax[sample] = m;
}

// ---------------------------------------------------------------------------
// Phase 1: per-chunk matrix product R_c = prod M_t, M_t = A diag(E_t).
// One warp per chunk. Lane (i = lane>>1, half h = lane&1) owns R[i][h*8+kk].
// ---------------------------------------------------------------------------
__global__ void __launch_bounds__(32) phase1_kernel() {
    int c = blockIdx.x;
    int lane = threadIdx.x;
    int b = c / NC, cl = c % NC;
    int i = lane >> 1, h = lane & 1;

    float a[KK][8];
    #pragma unroll
    for (int j = 0; j < KK; j++)
        #pragma unroll
        for (int kk = 0; kk < 8; kk++)
            a[j][kk] = g_A[j*KK + h*8 + kk];

    float R[8];
    #pragma unroll
    for (int kk = 0; kk < 8; kk++)
        R[kk] = (i == h*8 + kk) ? 1.f : 0.f;

    float rowlog = 0.f, rmsum = 0.f;

    int t0 = b*SS + cl*CH;
    int us = (cl == 0) ? 1 : 0;
    const float* prm = g_rowmax + t0;

    float E[8], En[8];
    {
        const float4* p4 = (const float4*)(g_E + (size_t)(t0 + us)*KK + h*8);
        float4 q0 = __ldg(p4+0), q1 = __ldg(p4+1);
        E[0]=q0.x; E[1]=q0.y; E[2]=q0.z; E[3]=q0.w;
        E[4]=q1.x; E[5]=q1.y; E[6]=q1.z; E[7]=q1.w;
    }
    float rmc = __ldg(prm + us), rmn = 0.f;

    for (int u = us; u < CH; u++) {
        if (u + 1 < CH) {
            const float4* p4 = (const float4*)(g_E + (size_t)(t0 + u + 1)*KK + h*8);
            float4 q0 = __ldg(p4+0), q1 = __ldg(p4+1);
            En[0]=q0.x; En[1]=q0.y; En[2]=q0.z; En[3]=q0.w;
            En[4]=q1.x; En[5]=q1.y; En[6]=q1.z; En[7]=q1.w;
            rmn = __ldg(prm + u + 1);
        }
        rmsum += rmc;

        float rp[8];
        #pragma unroll
        for (int j = 0; j < 8; j++) rp[j] = __shfl_xor_sync(FULL, R[j], 1);
        float rlo[8], rhi[8];
        #pragma unroll
        for (int j = 0; j < 8; j++) {
            rlo[j] = h ? rp[j] : R[j];
            rhi[j] = h ? R[j] : rp[j];
        }
        float nw[8];
        #pragma unroll
        for (int kk = 0; kk < 8; kk++) {
            float s0 = 0.f, s1 = 0.f;
            #pragma unroll
            for (int j = 0; j < 8; j++) {
                s0 = fmaf(rlo[j], a[j][kk],   s0);
                s1 = fmaf(rhi[j], a[j+8][kk], s1);
            }
            nw[kk] = (s0 + s1) * E[kk];
        }
        #pragma unroll
        for (int kk = 0; kk < 8; kk++) R[kk] = nw[kk];

        if (((u + 1) & 15) == 0) {
            float mx = R[0];
            #pragma unroll
            for (int kk = 1; kk < 8; kk++) mx = fmaxf(mx, R[kk]);
            mx = fmaxf(mx, __shfl_xor_sync(FULL, mx, 1));
            mx = fmaxf(mx, 1e-37f);
            float inv = __fdividef(1.f, mx);
            #pragma unroll
            for (int kk = 0; kk < 8; kk++) R[kk] *= inv;
            rowlog += __logf(mx);
        }

        #pragma unroll
        for (int kk = 0; kk < 8; kk++) E[kk] = En[kk];
        rmc = rmn;
    }

    #pragma unroll
    for (int kk = 0; kk < 8; kk++)
        g_Rn[c][i*KK + h*8 + kk] = R[kk];
    if (h == 0) g_rowlog[c][i] = rowlog;
    if (lane == 0) g_rmsum[c] = rmsum;
}

// ---------------------------------------------------------------------------
// Phase 2: one 256-thread block per batch.
// Staging warps build scaled chunk matrices in SMEM in parallel;
// warp 0 then runs the 32 sequential combines with a shfl-dot-only chain.
// ---------------------------------------------------------------------------
__global__ void __launch_bounds__(256) phase2_kernel(const float* __restrict__ start_logits) {
    __shared__ __align__(16) float Bs[NC][16][16];   // 32 KB
    __shared__ float rc[NC];                          // rmsum + rlmax per chunk

    int b = blockIdx.x;
    int tid = threadIdx.x;
    int w = tid >> 5, lane = tid & 31;
    int kk = lane & 15;

    // ---- staging: warp w handles chunks w, w+8, w+16, w+24 ----
    #pragma unroll
    for (int cc = 0; cc < NC/8; cc++) {
        int c = w + cc*8;
        int gc = b*NC + c;
        float rl = __ldg(&g_rowlog[gc][kk]);
        float rlmax = rl;
        #pragma unroll
        for (int off = 8; off; off >>= 1)
            rlmax = fmaxf(rlmax, __shfl_xor_sync(FULL, rlmax, off));
        float smy = __expf(rl - rlmax);
        #pragma unroll
        for (int i = 0; i < 16; i++) {
            float s = __shfl_sync(FULL, smy, i);
            if (lane < 16)
                Bs[c][i][kk] = s * __ldg(&g_Rn[gc][i*KK + kk]);
        }
        if (lane == 0) rc[c] = __ldg(&g_rmsum[gc]) + rlmax;
    }
    __syncthreads();

    if (w != 0) return;

    // ---- warp 0: init with step 0 ----
    float sv = __ldg(start_logits + kk);
    float sm = sv;
    #pragma unroll
    for (int off = 8; off; off >>= 1) sm = fmaxf(sm, __shfl_xor_sync(FULL, sm, off));
    float se = __expf(sv - sm);
    #pragma unroll
    for (int off = 8; off; off >>= 1) se += __shfl_xor_sync(FULL, se, off);
    float lstart = sv - sm - __logf(se);

    float e0 = __ldg(&g_emp[(size_t)(b*SS)*KK + kk]);
    float t = lstart + e0;
    float m0 = t;
    #pragma unroll
    for (int off = 8; off; off >>= 1) m0 = fmaxf(m0, __shfl_xor_sync(FULL, m0, off));
    float q = __expf(t - m0);
    float C = __ldg(&g_rowmax[b*SS]) + m0;

    // preload chunk 0 column
    float Bc[16], Bn[16];
    #pragma unroll
    for (int i = 0; i < 16; i++) Bc[i] = Bs[0][i][kk];

    for (int c = 0; c < NC; c++) {
        int gc = b*NC + c;
        if (c > 0) {
            if (lane < 16) g_qb[gc][kk] = q;
            if (lane == 0) g_Cb[gc] = C;
        }
        if (c + 1 < NC) {
            #pragma unroll
            for (int i = 0; i < 16; i++) Bn[i] = Bs[c+1][i][kk];
        }

        // v[kk] = sum_i q[i] * Bc[i]   (the only q-chain work)
        float s0 = 0.f, s1 = 0.f, s2 = 0.f, s3 = 0.f;
        #pragma unroll
        for (int j = 0; j < 16; j += 4) {
            s0 = fmaf(__shfl_sync(FULL, q, j + 0), Bc[j + 0], s0);
            s1 = fmaf(__shfl_sync(FULL, q, j + 1), Bc[j + 1], s1);
            s2 = fmaf(__shfl_sync(FULL, q, j + 2), Bc[j + 2], s2);
            s3 = fmaf(__shfl_sync(FULL, q, j + 3), Bc[j + 3], s3);
        }
        float v = (s0 + s1) + (s2 + s3);
        C += rc[c];

        // renorm every 8 chunks (growth <= 16^8, shrink >= ~1e-17: fp32-safe)
        if ((c & 7) == 7) {
            float mv = v;
            #pragma unroll
            for (int off = 8; off; off >>= 1)
                mv = fmaxf(mv, __shfl_xor_sync(FULL, mv, off));
            mv = fmaxf(mv, 1e-37f);
            q = __fdividef(v, mv);
            C += __logf(mv);
        } else {
            q = v;
        }

        #pragma unroll
        for (int i = 0; i < 16; i++) Bc[i] = Bn[i];
    }
}

// ---------------------------------------------------------------------------
// Phase 3: per-chunk vector recursion from stored boundary, writes outputs.
// ---------------------------------------------------------------------------
__global__ void __launch_bounds__(32) phase3_kernel(
    const float* __restrict__ start_logits, float* __restrict__ out)
{
    int c = blockIdx.x;
    int lane = threadIdx.x;
    int b = c / NC, cl = c % NC;
    int kk = lane & 15;

    float acol[KK];
    #pragma unroll
    for (int j = 0; j < KK; j++) acol[j] = __ldg(&g_A[j*KK + kk]);

    const float* pE = g_E   + (size_t)(b*SS + cl*CH)*KK;
    const float* pP = g_emp + (size_t)(b*SS + cl*CH)*KK;
    const float* prm = g_rowmax + b*SS + cl*CH;
    float* ob = out + (size_t)(b*SS + cl*CH)*KK;

    float bufEA[16], bufPA[16], bufEB[16], bufPB[16];
    float rmA[16], rmB[16];
    #pragma unroll
    for (int u = 0; u < 16; u++) {
        bufEA[u] = __ldg(pE + u*KK + kk);
        bufPA[u] = __ldg(pP + u*KK + kk);
        rmA[u]   = __ldg(prm + u);
    }

    float q, C;
    if (cl == 0) {
        float sv = __ldg(start_logits + kk);
        float sm = sv;
        #pragma unroll
        for (int off = 8; off; off >>= 1) sm = fmaxf(sm, __shfl_xor_sync(FULL, sm, off));
        float se = __expf(sv - sm);
        #pragma unroll
        for (int off = 8; off; off >>= 1) se += __shfl_xor_sync(FULL, se, off);
        float lstart = sv - sm - __logf(se);

        float a0 = lstart + bufPA[0] + rmA[0];
        if (lane < 16) ob[kk] = a0;
        q = __expf(fmaxf(lstart + bufPA[0], -80.f));
        C = rmA[0];
    } else {
        q = __ldg(&g_qb[c][kk]);
        C = __ldg(&g_Cb[c]);
    }

    const int NSB = CH / 16;  // 4
    for (int sb = 0; sb < NSB; sb++) {
        if (sb + 1 < NSB) {
            #pragma unroll
            for (int u = 0; u < 16; u++) {
                bufEB[u] = __ldg(pE + ((sb+1)*16 + u)*KK + kk);
                bufPB[u] = __ldg(pP + ((sb+1)*16 + u)*KK + kk);
                rmB[u]   = __ldg(prm + (sb+1)*16 + u);
            }
        }
        #pragma unroll
        for (int u = 0; u < 16; u++) {
            if (sb == 0 && u == 0 && cl == 0) continue;
            float s0 = 0.f, s1 = 0.f, s2 = 0.f, s3 = 0.f;
            #pragma unroll
            for (int j = 0; j < KK; j += 4) {
                s0 = fmaf(__shfl_sync(FULL, q, j + 0), acol[j + 0], s0);
                s1 = fmaf(__shfl_sync(FULL, q, j + 1), acol[j + 1], s1);
                s2 = fmaf(__shfl_sync(FULL, q, j + 2), acol[j + 2], s2);
                s3 = fmaf(__shfl_sync(FULL, q, j + 3), acol[j + 3], s3);
            }
            float ssum = (s0 + s1) + (s2 + s3);
            float ov = C + rmA[u] + bufPA[u] + __logf(ssum);
            if (lane < 16) ob[(sb*16 + u)*KK + kk] = ov;
            q = ssum * bufEA[u];
            C += rmA[u];
        }
        float mq = q;
        #pragma unroll
        for (int off = 16; off; off >>= 1)
            mq = fmaxf(mq, __shfl_xor_sync(FULL, mq, off));
        q = __fdividef(q, mq);
        C += __logf(mq);

        if (sb + 1 < NSB) {
            #pragma unroll
            for (int u = 0; u < 16; u++) {
                bufEA[u] = bufEB[u]; bufPA[u] = bufPB[u]; rmA[u] = rmB[u];
            }
        }
    }
}

// ---------------------------------------------------------------------------
extern "C" void kernel_launch(void* const* d_in, const int* in_sizes, int n_in,
                              void* d_out, int out_size) {
    const float* y   = (const float*)d_in[0];
    const float* z   = (const float*)d_in[1];
    const float* st  = (const float*)d_in[2];
    const float* tr  = (const float*)d_in[3];
    const float* mu  = (const float*)d_in[4];
    const float* lv  = (const float*)d_in[5];
    const float* wz  = (const float*)d_in[6];
    const float* ws  = (const float*)d_in[7];
    const float* bd  = (const float*)d_in[8];
    float* out = (float*)d_out;

    setup_kernel<<<KK, 32>>>(lv, ws, tr);
    emissions_kernel<<<NS/SPB, TPB>>>(y, z, wz, ws, bd, mu);
    phase1_kernel<<<TOTCH, 32>>>();
    phase2_kernel<<<BB, 256>>>(st);
    phase3_kernel<<<TOTCH, 32>>>(st, out);
}